// round 1
// baseline (speedup 1.0000x reference)
#include <cuda_runtime.h>
#include <cuda_bf16.h>

#define N_NODES 65536
#define N_EDGES 65536
#define DF      128
#define NNZ_CNT (1 << 20)

// ---------------- scratch (device globals; no cudaMalloc allowed) ----------
__device__ int   g_cnt_n[N_NODES];
__device__ int   g_cnt_e[N_EDGES];
__device__ float g_degn[N_NODES];          // weighted node degree
__device__ float g_dinv[N_NODES];          // 1/deg_n
__device__ float g_se[N_EDGES];            // w_e / deg_e (folds B^-1 and w)
__device__ int   g_off_e[N_EDGES + 1];
__device__ int   g_off_n[N_NODES + 1];
__device__ int   g_cur_e[N_EDGES];
__device__ int   g_cur_n[N_NODES];
__device__ int   g_csr_e[NNZ_CNT];         // node ids grouped by edge
__device__ int   g_csr_n[NNZ_CNT];         // edge ids grouped by node
__device__ __align__(16) float g_y[N_NODES * DF];
__device__ __align__(16) float g_ef[N_EDGES * DF];
__device__ __align__(16) float g_h[N_NODES * DF];

// ---------------- kernels --------------------------------------------------
__global__ void k_zero() {
    int i = blockIdx.x * blockDim.x + threadIdx.x;
    if (i < N_NODES) { g_cnt_n[i] = 0; g_degn[i] = 0.f; }
    if (i < N_EDGES) { g_cnt_e[i] = 0; }
}

__global__ void k_hist(const int* __restrict__ nidx, const int* __restrict__ eidx,
                       const float* __restrict__ w) {
    int i = blockIdx.x * blockDim.x + threadIdx.x;
    if (i < NNZ_CNT) {
        int n = nidx[i];
        int e = eidx[i];
        atomicAdd(&g_cnt_n[n], 1);
        atomicAdd(&g_cnt_e[e], 1);
        atomicAdd(&g_degn[n], w[e]);
    }
}

// exclusive scan of 65536 ints with one 1024-thread block (64 elems/thread)
__global__ void k_scan(const int* __restrict__ cnt, int* __restrict__ off,
                       int* __restrict__ cur, int n) {
    __shared__ int ss[1024];
    int t = threadIdx.x;
    int per = n >> 10;             // 64
    int base = t * per;
    int s = 0;
    for (int i = 0; i < per; i++) s += cnt[base + i];
    ss[t] = s;
    __syncthreads();
    for (int d = 1; d < 1024; d <<= 1) {
        int v = (t >= d) ? ss[t - d] : 0;
        __syncthreads();
        ss[t] += v;
        __syncthreads();
    }
    int run = (t > 0) ? ss[t - 1] : 0;
    for (int i = 0; i < per; i++) {
        int c = cnt[base + i];
        off[base + i] = run;
        cur[base + i] = run;
        run += c;
    }
    if (t == 1023) off[n] = run;
}

__global__ void k_scales(const float* __restrict__ w) {
    int i = blockIdx.x * blockDim.x + threadIdx.x;
    if (i < N_EDGES) {
        int c = g_cnt_e[i];
        g_se[i] = (c > 0) ? (w[i] / (float)c) : 0.f;
    }
    if (i < N_NODES) {
        float d = g_degn[i];
        g_dinv[i] = (d > 0.f) ? (1.f / d) : 0.f;
    }
}

__global__ void k_build(const int* __restrict__ nidx, const int* __restrict__ eidx) {
    int i = blockIdx.x * blockDim.x + threadIdx.x;
    if (i < NNZ_CNT) {
        int n = nidx[i];
        int e = eidx[i];
        int p = atomicAdd(&g_cur_e[e], 1);
        g_csr_e[p] = n;
        int q = atomicAdd(&g_cur_n[n], 1);
        g_csr_n[q] = e;
    }
}

// C[row,:] = A[row,:] @ W   (A: [nrows,128], W: [128,128] row-major)
// block = 256 threads, 64 rows/block. smem: W(64KB) + Xtile(32KB) = 96KB.
__global__ void k_gemm(const float* __restrict__ A, const float* __restrict__ W,
                       float* __restrict__ C) {
    extern __shared__ float sm[];
    float4* sW4 = (float4*)sm;                 // 128*32 float4
    float4* sX4 = (float4*)(sm + DF * DF);     // 64*32 float4
    int tid = threadIdx.x;

    const float4* W4 = (const float4*)W;
    for (int i = tid; i < DF * DF / 4; i += 256) sW4[i] = W4[i];

    int row0 = blockIdx.x * 64;
    const float4* A4 = (const float4*)(A + (size_t)row0 * DF);
    for (int i = tid; i < 64 * DF / 4; i += 256) sX4[i] = A4[i];
    __syncthreads();

    int warp = tid >> 5, lane = tid & 31;
    float4 acc[8];
#pragma unroll
    for (int r = 0; r < 8; r++) acc[r] = make_float4(0.f, 0.f, 0.f, 0.f);

    for (int k0 = 0; k0 < DF; k0 += 4) {
        float4 w0 = sW4[(k0 + 0) * 32 + lane];
        float4 w1 = sW4[(k0 + 1) * 32 + lane];
        float4 w2 = sW4[(k0 + 2) * 32 + lane];
        float4 w3 = sW4[(k0 + 3) * 32 + lane];
#pragma unroll
        for (int r = 0; r < 8; r++) {
            float4 xv = sX4[(warp * 8 + r) * 32 + (k0 >> 2)];  // broadcast
            acc[r].x += xv.x * w0.x + xv.y * w1.x + xv.z * w2.x + xv.w * w3.x;
            acc[r].y += xv.x * w0.y + xv.y * w1.y + xv.z * w2.y + xv.w * w3.y;
            acc[r].z += xv.x * w0.z + xv.y * w1.z + xv.z * w2.z + xv.w * w3.z;
            acc[r].w += xv.x * w0.w + xv.y * w1.w + xv.z * w2.w + xv.w * w3.w;
        }
    }

    float4* C4 = (float4*)C;
#pragma unroll
    for (int r = 0; r < 8; r++)
        C4[(size_t)(row0 + warp * 8 + r) * 32 + lane] = acc[r];
}

// one warp per segment: dst[seg,:] = (sum_{j in seg} src[idx[j],:]) * scale[seg]
//                                    (+ bias) (relu?)
__global__ void k_agg(const float* __restrict__ src, float* __restrict__ dst,
                      const int* __restrict__ off, const int* __restrict__ idx,
                      const float* __restrict__ scale, const float* __restrict__ bias,
                      int relu, int nseg) {
    int gwarp = (blockIdx.x * blockDim.x + threadIdx.x) >> 5;
    int lane = threadIdx.x & 31;
    if (gwarp >= nseg) return;
    int s = off[gwarp], e = off[gwarp + 1];
    const float4* s4 = (const float4*)src;

    float4 a0 = make_float4(0.f, 0.f, 0.f, 0.f);
    float4 a1 = make_float4(0.f, 0.f, 0.f, 0.f);
    int j = s;
    for (; j + 1 < e; j += 2) {
        int r0 = idx[j];
        int r1 = idx[j + 1];
        float4 v0 = s4[(size_t)r0 * 32 + lane];
        float4 v1 = s4[(size_t)r1 * 32 + lane];
        a0.x += v0.x; a0.y += v0.y; a0.z += v0.z; a0.w += v0.w;
        a1.x += v1.x; a1.y += v1.y; a1.z += v1.z; a1.w += v1.w;
    }
    if (j < e) {
        int r = idx[j];
        float4 v = s4[(size_t)r * 32 + lane];
        a0.x += v.x; a0.y += v.y; a0.z += v.z; a0.w += v.w;
    }
    float sc = scale[gwarp];
    float4 o;
    o.x = (a0.x + a1.x) * sc;
    o.y = (a0.y + a1.y) * sc;
    o.z = (a0.z + a1.z) * sc;
    o.w = (a0.w + a1.w) * sc;
    if (bias) {
        float4 bb = ((const float4*)bias)[lane];
        o.x += bb.x; o.y += bb.y; o.z += bb.z; o.w += bb.w;
    }
    if (relu) {
        o.x = fmaxf(o.x, 0.f); o.y = fmaxf(o.y, 0.f);
        o.z = fmaxf(o.z, 0.f); o.w = fmaxf(o.w, 0.f);
    }
    ((float4*)dst)[(size_t)gwarp * 32 + lane] = o;
}

// ---------------- launch ---------------------------------------------------
extern "C" void kernel_launch(void* const* d_in, const int* in_sizes, int n_in,
                              void* d_out, int out_size) {
    const float* x   = (const float*)d_in[0];
    const int*   hei = (const int*)d_in[1];
    const float* w   = (const float*)d_in[2];
    const float* W1  = (const float*)d_in[3];
    const float* b1  = (const float*)d_in[4];
    const float* W2  = (const float*)d_in[5];
    const float* b2  = (const float*)d_in[6];
    float* out = (float*)d_out;

    const int* nidx = hei;
    const int* eidx = hei + NNZ_CNT;

    // resolve device-global addresses (host API, capture-safe)
    int *p_cnt_e, *p_cnt_n, *p_off_e, *p_off_n, *p_cur_e, *p_cur_n, *p_csr_e, *p_csr_n;
    float *p_y, *p_ef, *p_h, *p_se, *p_dinv;
    cudaGetSymbolAddress((void**)&p_cnt_e, g_cnt_e);
    cudaGetSymbolAddress((void**)&p_cnt_n, g_cnt_n);
    cudaGetSymbolAddress((void**)&p_off_e, g_off_e);
    cudaGetSymbolAddress((void**)&p_off_n, g_off_n);
    cudaGetSymbolAddress((void**)&p_cur_e, g_cur_e);
    cudaGetSymbolAddress((void**)&p_cur_n, g_cur_n);
    cudaGetSymbolAddress((void**)&p_csr_e, g_csr_e);
    cudaGetSymbolAddress((void**)&p_csr_n, g_csr_n);
    cudaGetSymbolAddress((void**)&p_y,    g_y);
    cudaGetSymbolAddress((void**)&p_ef,   g_ef);
    cudaGetSymbolAddress((void**)&p_h,    g_h);
    cudaGetSymbolAddress((void**)&p_se,   g_se);
    cudaGetSymbolAddress((void**)&p_dinv, g_dinv);

    cudaFuncSetAttribute(k_gemm, cudaFuncAttributeMaxDynamicSharedMemorySize, 98304);

    // -------- shared preprocessing (both layers use the same incidence) ----
    k_zero<<<256, 256>>>();
    k_hist<<<NNZ_CNT / 256, 256>>>(nidx, eidx, w);
    k_scan<<<1, 1024>>>(p_cnt_e, p_off_e, p_cur_e, N_EDGES);
    k_scan<<<1, 1024>>>(p_cnt_n, p_off_n, p_cur_n, N_NODES);
    k_scales<<<256, 256>>>(w);
    k_build<<<NNZ_CNT / 256, 256>>>(nidx, eidx);

    const int AGG_BLOCKS = N_NODES / 8;  // 8 warps per 256-thread block

    // -------- layer 1 ------------------------------------------------------
    k_gemm<<<N_NODES / 64, 256, 98304>>>(x, W1, p_y);
    k_agg<<<AGG_BLOCKS, 256>>>(p_y, p_ef, p_off_e, p_csr_e, p_se, nullptr, 0, N_EDGES);
    k_agg<<<AGG_BLOCKS, 256>>>(p_ef, p_h, p_off_n, p_csr_n, p_dinv, b1, 1, N_NODES);

    // -------- layer 2 ------------------------------------------------------
    k_gemm<<<N_NODES / 64, 256, 98304>>>(p_h, W2, p_y);
    k_agg<<<AGG_BLOCKS, 256>>>(p_y, p_ef, p_off_e, p_csr_e, p_se, nullptr, 0, N_EDGES);
    k_agg<<<AGG_BLOCKS, 256>>>(p_ef, out, p_off_n, p_csr_n, p_dinv, b2, 0, N_NODES);
}